// round 2
// baseline (speedup 1.0000x reference)
#include <cuda_runtime.h>
#include <cuda_bf16.h>

// Problem constants
#define BB 2
#define SS 2048
#define DD 1024
#define HH 16
#define HD 64
#define M_ROWS (BB*SS)          // 4096
#define QKV_N  (3*DD)           // 3072

// Scratch (allocation-free: __device__ globals)
__device__ float g_q[BB*HH*SS*HD];     // [B,H,S,HD]
__device__ float g_k[BB*HH*SS*HD];
__device__ float g_v[BB*HH*SS*HD];
__device__ float g_attn[M_ROWS*DD];    // [B*S, D]

// ---------------------------------------------------------------------------
// SGEMM: C[M,N] = A[M,K] @ B[K,N] + bias[N]
// 128x128 block tile, BK=8, 256 threads, 8x8 per-thread register tile.
// qkv_mode=1: scatter into g_q/g_k/g_v with [B,H,S,HD] layout.
// qkv_mode=0: plain row-major write to C. A==nullptr means read g_attn.
// ---------------------------------------------------------------------------
__global__ __launch_bounds__(256) void sgemm_kernel(
    const float* __restrict__ A, const float* __restrict__ B,
    const float* __restrict__ bias, float* __restrict__ C,
    int M, int N, int K, int qkv_mode)
{
    __shared__ float As[8][128];
    __shared__ float Bs[8][128];

    if (A == nullptr) A = g_attn;

    const int tid = threadIdx.x;
    const int bm = blockIdx.y, bn = blockIdx.x;

    // A-tile load mapping: each thread one float4
    const int aRow = tid >> 1;          // 0..127
    const int aCol = (tid & 1) * 4;     // 0 or 4
    // B-tile load mapping
    const int bRow = tid >> 5;          // 0..7
    const int bCol = (tid & 31) * 4;    // 0..124

    const float* Ablk = A + (size_t)(bm * 128) * K;
    const float* Bblk = B + bn * 128;

    const int tx = tid & 15, ty = tid >> 4;

    float acc[8][8];
#pragma unroll
    for (int i = 0; i < 8; i++)
#pragma unroll
        for (int j = 0; j < 8; j++) acc[i][j] = 0.0f;

    for (int kt = 0; kt < K; kt += 8) {
        float4 av = *(const float4*)(Ablk + (size_t)aRow * K + kt + aCol);
        As[aCol + 0][aRow] = av.x;
        As[aCol + 1][aRow] = av.y;
        As[aCol + 2][aRow] = av.z;
        As[aCol + 3][aRow] = av.w;
        *(float4*)(&Bs[bRow][bCol]) =
            *(const float4*)(Bblk + (size_t)(kt + bRow) * N + bCol);
        __syncthreads();

#pragma unroll
        for (int k = 0; k < 8; k++) {
            float a[8], b[8];
            *(float4*)(a)     = *(const float4*)(&As[k][ty * 8]);
            *(float4*)(a + 4) = *(const float4*)(&As[k][ty * 8 + 4]);
            *(float4*)(b)     = *(const float4*)(&Bs[k][tx * 8]);
            *(float4*)(b + 4) = *(const float4*)(&Bs[k][tx * 8 + 4]);
#pragma unroll
            for (int i = 0; i < 8; i++)
#pragma unroll
                for (int j = 0; j < 8; j++)
                    acc[i][j] = fmaf(a[i], b[j], acc[i][j]);
        }
        __syncthreads();
    }

    const int row0 = bm * 128 + ty * 8;
    const int col0 = bn * 128 + tx * 8;

    if (qkv_mode) {
#pragma unroll
        for (int i = 0; i < 8; i++) {
            const int row = row0 + i;
            const int b_ = row >> 11;        // /2048
            const int s_ = row & 2047;
#pragma unroll
            for (int j = 0; j < 8; j++) {
                const int col = col0 + j;
                const float v = acc[i][j] + bias[col];
                const int which = col >> 10;         // 0=q,1=k,2=v
                const int h  = (col >> 6) & 15;
                const int hd = col & 63;
                float* dst = (which == 0) ? g_q : (which == 1) ? g_k : g_v;
                dst[(((size_t)(b_ * HH + h) * SS) + s_) * HD + hd] = v;
            }
        }
    } else {
#pragma unroll
        for (int i = 0; i < 8; i++) {
            const int row = row0 + i;
#pragma unroll
            for (int j = 0; j < 8; j++) {
                const int col = col0 + j;
                C[(size_t)row * N + col] = acc[i][j] + bias[col];
            }
        }
    }
}

// ---------------------------------------------------------------------------
// Flash attention: per block = one (b, h, 64-row q tile).
// 256 threads: thread t -> q-row r = t/4, column-group c4 = t%4.
// Smem: Qs/Ks/Vs 64x64 tiles padded to stride 68 (conflict-free, 16B-aligned
// rows for float4 LDS). Online softmax, p exchanged via shfl within the
// 4-lane row group. Writes [B*S, D] layout into g_attn.
// ---------------------------------------------------------------------------
#define TSTRIDE 68
#define ATTN_SMEM (3 * 64 * TSTRIDE * 4)

__global__ __launch_bounds__(256) void attn_kernel()
{
    extern __shared__ __align__(16) float sm[];
    float* Qs = sm;
    float* Ks = sm + 64 * TSTRIDE;
    float* Vs = sm + 2 * 64 * TSTRIDE;

    const int tid = threadIdx.x;
    const int qt = blockIdx.x;     // 0..31
    const int h  = blockIdx.y;     // 0..15
    const int b  = blockIdx.z;     // 0..1
    const int r  = tid >> 2;       // 0..63
    const int c4 = tid & 3;        // 0..3
    const int lane = tid & 31;
    const unsigned FULL = 0xffffffffu;

    const float* Qg = g_q + ((size_t)(b * HH + h) * SS + qt * 64) * HD;
    const float* Kg = g_k + ((size_t)(b * HH + h) * SS) * HD;
    const float* Vg = g_v + ((size_t)(b * HH + h) * SS) * HD;

    // Load Q tile (pre-scaled by 1/sqrt(64))
    for (int e = tid; e < 64 * 64; e += 256) {
        const int rr = e >> 6, d = e & 63;
        Qs[rr * TSTRIDE + d] = Qg[e] * 0.125f;
    }

    float acc[16];
#pragma unroll
    for (int i = 0; i < 16; i++) acc[i] = 0.0f;
    float m = -1e30f, l = 0.0f;

    for (int kt = 0; kt < SS / 64; kt++) {
        __syncthreads();   // previous tile fully consumed (and Qs visible, iter 0)
        for (int e = tid; e < 64 * 64; e += 256) {
            const int rr = e >> 6, d = e & 63;
            Ks[rr * TSTRIDE + d] = Kg[(size_t)kt * 4096 + e];
            Vs[rr * TSTRIDE + d] = Vg[(size_t)kt * 4096 + e];
        }
        __syncthreads();

        // scores: s[j] = Q[r,:] . K[c4+4j,:]
        float s[16];
#pragma unroll
        for (int j = 0; j < 16; j++) s[j] = 0.0f;
#pragma unroll
        for (int d4 = 0; d4 < 16; d4++) {
            const float4 qv = *(const float4*)&Qs[r * TSTRIDE + d4 * 4];
#pragma unroll
            for (int j = 0; j < 16; j++) {
                const int kc = c4 + 4 * j;
                const float4 kv = *(const float4*)&Ks[kc * TSTRIDE + d4 * 4];
                s[j] += qv.x * kv.x + qv.y * kv.y + qv.z * kv.z + qv.w * kv.w;
            }
        }

        // row max across this thread's 16 + the 4-lane group
        float mt = s[0];
#pragma unroll
        for (int j = 1; j < 16; j++) mt = fmaxf(mt, s[j]);
        mt = fmaxf(mt, __shfl_xor_sync(FULL, mt, 1));
        mt = fmaxf(mt, __shfl_xor_sync(FULL, mt, 2));

        const float m_new = fmaxf(m, mt);
        const float alpha = __expf(m - m_new);
        float ls = 0.0f;
#pragma unroll
        for (int j = 0; j < 16; j++) {
            s[j] = __expf(s[j] - m_new);
            ls += s[j];
        }
        ls += __shfl_xor_sync(FULL, ls, 1);
        ls += __shfl_xor_sync(FULL, ls, 2);
        l = l * alpha + ls;
        m = m_new;
#pragma unroll
        for (int i = 0; i < 16; i++) acc[i] *= alpha;

        // PV: acc[c] += sum_kc p[kc] * V[kc, c], c = c4*16 + i
#pragma unroll
        for (int jj = 0; jj < 16; jj++) {
            const float pj = s[jj];
#pragma unroll
            for (int c4s = 0; c4s < 4; c4s++) {
                const float pv = __shfl_sync(FULL, pj, (lane & ~3) | c4s);
                const int kc = c4s + 4 * jj;
                const float* vrow = &Vs[kc * TSTRIDE + c4 * 16];
#pragma unroll
                for (int i4 = 0; i4 < 4; i4++) {
                    const float4 vv = *(const float4*)(vrow + i4 * 4);
                    acc[i4 * 4 + 0] = fmaf(pv, vv.x, acc[i4 * 4 + 0]);
                    acc[i4 * 4 + 1] = fmaf(pv, vv.y, acc[i4 * 4 + 1]);
                    acc[i4 * 4 + 2] = fmaf(pv, vv.z, acc[i4 * 4 + 2]);
                    acc[i4 * 4 + 3] = fmaf(pv, vv.w, acc[i4 * 4 + 3]);
                }
            }
        }
    }

    const float inv = 1.0f / l;
    const int orow = b * SS + qt * 64 + r;
    const int ocol0 = h * HD + c4 * 16;
    float* out = g_attn + (size_t)orow * DD + ocol0;
#pragma unroll
    for (int i = 0; i < 16; i++) out[i] = acc[i] * inv;
}

// ---------------------------------------------------------------------------
extern "C" void kernel_launch(void* const* d_in, const int* in_sizes, int n_in,
                              void* d_out, int out_size)
{
    const float* x      = (const float*)d_in[0];
    const float* w_qkv  = (const float*)d_in[1];
    const float* b_qkv  = (const float*)d_in[2];
    const float* w_proj = (const float*)d_in[3];
    const float* b_proj = (const float*)d_in[4];
    float* out = (float*)d_out;

    cudaFuncSetAttribute(attn_kernel,
                         cudaFuncAttributeMaxDynamicSharedMemorySize, ATTN_SMEM);

    // GEMM1: [4096,1024] @ [1024,3072] -> scatter Q/K/V
    {
        dim3 grid(QKV_N / 128, M_ROWS / 128);
        sgemm_kernel<<<grid, 256>>>(x, w_qkv, b_qkv, nullptr,
                                    M_ROWS, QKV_N, DD, 1);
    }
    // Attention: 32 q-tiles x 16 heads x 2 batches
    {
        dim3 grid(SS / 64, HH, BB);
        attn_kernel<<<grid, 256, ATTN_SMEM>>>();
    }
    // GEMM2: [4096,1024] @ [1024,1024] + bias -> out
    {
        dim3 grid(DD / 128, M_ROWS / 128);
        sgemm_kernel<<<grid, 256>>>(nullptr, w_proj, b_proj, out,
                                    M_ROWS, DD, DD, 0);
    }
}

// round 6
// speedup vs baseline: 5.2523x; 5.2523x over previous
#include <cuda_runtime.h>
#include <cuda_bf16.h>
#include <cstdint>

// Problem constants
#define BB 2
#define SS 2048
#define DD 1024
#define HH 16
#define HD 64
#define M_ROWS (BB*SS)          // 4096
#define QKV_N  (3*DD)           // 3072

// Scratch (allocation-free: __device__ globals)
__device__ float g_q[BB*HH*SS*HD];     // [B,H,S,HD]
__device__ float g_k[BB*HH*SS*HD];
__device__ float g_v[BB*HH*SS*HD];
__device__ float g_attn[M_ROWS*DD];    // [B*S, D]

// ---------------------------------------------------------------------------
// tf32 helpers (plain sm_80+ PTX -- no 'a'-suffix features)
// ---------------------------------------------------------------------------
__device__ __forceinline__ uint32_t f2tf(float f) {
    uint32_t u;
    asm("cvt.rna.tf32.f32 %0, %1;" : "=r"(u) : "f"(f));
    return u;
}
// D += A(16x8 tf32) * B(8x8 tf32), fp32 accum
__device__ __forceinline__ void mma8(float c[4], const uint32_t a[4], const uint32_t b[2]) {
    asm volatile(
        "mma.sync.aligned.m16n8k8.row.col.f32.tf32.tf32.f32 "
        "{%0,%1,%2,%3}, {%4,%5,%6,%7}, {%8,%9}, {%0,%1,%2,%3};"
        : "+f"(c[0]), "+f"(c[1]), "+f"(c[2]), "+f"(c[3])
        : "r"(a[0]), "r"(a[1]), "r"(a[2]), "r"(a[3]), "r"(b[0]), "r"(b[1]));
}

// ---------------------------------------------------------------------------
// tf32 mma.sync GEMM: C[M,N] = A[M,K] @ B[K,N] + bias
// CTA 128x128, BK=32, double-buffered smem, 8 warps as 4(m) x 2(n),
// warp tile 32x64 = 2 m16 x 8 n8 frags. cvt.rna at staging.
// qkv_mode=1: scatter into g_q/g_k/g_v. A==nullptr -> read g_attn.
// ---------------------------------------------------------------------------
#define AST 36    // A smem row stride (floats): 36 % 32 = 4 -> conflict-free frags
#define BST 132   // B smem row stride
#define GEMM_SMEM ((2*128*AST + 2*32*BST)*4)   // 70656 B

__global__ __launch_bounds__(256) void tc_gemm(
    const float* __restrict__ A, const float* __restrict__ B,
    const float* __restrict__ bias, float* __restrict__ C,
    int M, int N, int K, int qkv_mode)
{
    extern __shared__ float sh[];
    float* As[2] = { sh, sh + 128*AST };
    float* Bs[2] = { sh + 2*128*AST, sh + 2*128*AST + 32*BST };

    const int tid = threadIdx.x;
    const int wid = tid >> 5, lane = tid & 31;
    const int g = lane >> 2, t = lane & 3;
    const int bm = blockIdx.y, bn = blockIdx.x;
    const int wm = wid & 3, wn = wid >> 2;     // warp: rows wm*32, cols wn*64

    if (A == nullptr) A = g_attn;
    const float* Ablk = A + (size_t)bm * 128 * K;
    const float* Bblk = B + (size_t)bn * 128;

    float acc[2][8][4];
#pragma unroll
    for (int i = 0; i < 2; i++)
#pragma unroll
        for (int j = 0; j < 8; j++)
#pragma unroll
            for (int k = 0; k < 4; k++) acc[i][j][k] = 0.0f;

    float4 ar[4], br[4];
    auto LDG = [&](int kt) {
#pragma unroll
        for (int i = 0; i < 4; i++) {       // A tile 128x32: 8 float4/row
            int f = tid + i * 256;
            ar[i] = *(const float4*)(Ablk + (size_t)(f >> 3) * K + kt * 32 + (f & 7) * 4);
        }
#pragma unroll
        for (int i = 0; i < 4; i++) {       // B tile 32x128: 32 float4/row
            int f = tid + i * 256;
            br[i] = *(const float4*)(Bblk + (size_t)(kt * 32 + (f >> 5)) * N + (f & 31) * 4);
        }
    };
    auto STS = [&](int p) {
#pragma unroll
        for (int i = 0; i < 4; i++) {
            int f = tid + i * 256;
            float* d = As[p] + (f >> 3) * AST + (f & 7) * 4;
            d[0] = __uint_as_float(f2tf(ar[i].x));
            d[1] = __uint_as_float(f2tf(ar[i].y));
            d[2] = __uint_as_float(f2tf(ar[i].z));
            d[3] = __uint_as_float(f2tf(ar[i].w));
        }
#pragma unroll
        for (int i = 0; i < 4; i++) {
            int f = tid + i * 256;
            float* d = Bs[p] + (f >> 5) * BST + (f & 31) * 4;
            d[0] = __uint_as_float(f2tf(br[i].x));
            d[1] = __uint_as_float(f2tf(br[i].y));
            d[2] = __uint_as_float(f2tf(br[i].z));
            d[3] = __uint_as_float(f2tf(br[i].w));
        }
    };

    const int NT = K >> 5;
    LDG(0); STS(0);
    if (NT > 1) LDG(1);
    __syncthreads();

    for (int kt = 0; kt < NT; kt++) {
        const int p = kt & 1;
        const float* Ab = As[p] + wm * 32 * AST;
        const float* Bb = Bs[p] + wn * 64;
#pragma unroll
        for (int ks = 0; ks < 4; ks++) {
            uint32_t af[2][4];
#pragma unroll
            for (int mt = 0; mt < 2; mt++) {
                const float* ap = Ab + (mt * 16 + g) * AST + ks * 8 + t;
                af[mt][0] = __float_as_uint(ap[0]);
                af[mt][1] = __float_as_uint(ap[8 * AST]);
                af[mt][2] = __float_as_uint(ap[4]);
                af[mt][3] = __float_as_uint(ap[8 * AST + 4]);
            }
#pragma unroll
            for (int nt = 0; nt < 8; nt++) {
                uint32_t bf[2];
                const float* bp = Bb + (ks * 8 + t) * BST + nt * 8 + g;
                bf[0] = __float_as_uint(bp[0]);
                bf[1] = __float_as_uint(bp[4 * BST]);
                mma8(acc[0][nt], af[0], bf);
                mma8(acc[1][nt], af[1], bf);
            }
        }
        if (kt + 1 < NT) {
            __syncthreads();            // everyone done reading buf p^1
            STS((kt + 1) & 1);
            if (kt + 2 < NT) LDG(kt + 2);
            __syncthreads();            // new tile visible
        }
    }

    // Epilogue: c0=(g,2t) c1=(g,2t+1) c2=(g+8,2t) c3=(g+8,2t+1)
#pragma unroll
    for (int mt = 0; mt < 2; mt++) {
#pragma unroll
        for (int half = 0; half < 2; half++) {
            const int row = bm * 128 + wm * 32 + mt * 16 + g + half * 8;
#pragma unroll
            for (int nt = 0; nt < 8; nt++) {
                const int col = bn * 128 + wn * 64 + nt * 8 + 2 * t;
                float2 v;
                v.x = acc[mt][nt][half * 2 + 0] + bias[col];
                v.y = acc[mt][nt][half * 2 + 1] + bias[col + 1];
                if (qkv_mode) {
                    const int b_ = row >> 11, s_ = row & 2047;
                    const int which = col >> 10;
                    const int h  = (col >> 6) & 15;
                    const int hd = col & 63;
                    float* dst = (which == 0) ? g_q : (which == 1) ? g_k : g_v;
                    *(float2*)&dst[(((size_t)(b_ * HH + h) * SS) + s_) * HD + hd] = v;
                } else {
                    *(float2*)&C[(size_t)row * N + col] = v;
                }
            }
        }
    }
}

// ---------------------------------------------------------------------------
// Flash attention on tf32 mma.sync. CTA = (b, h, 128 q-rows); 8 warps, each
// owns 16 q-rows. Q fragments register-resident (pre-scaled 1/8, tf32).
// K/V 64-row tiles in smem (stride 68 -> conflict-free 4g+t frag pattern).
// P goes through per-warp-private smem rows (C-frag -> A-frag relayout).
// ---------------------------------------------------------------------------
#define TST 68
#define ATT_SMEM ((2*64*TST + 128*TST)*4)   // Ks,Vs,Ps = 69632 B

__global__ __launch_bounds__(256) void attn_kernel()
{
    extern __shared__ float sh[];
    float* Ks = sh;
    float* Vs = sh + 64 * TST;
    float* Ps = sh + 2 * 64 * TST;

    const int tid = threadIdx.x;
    const int wid = tid >> 5, lane = tid & 31;
    const int g = lane >> 2, t = lane & 3;
    const int qt = blockIdx.x, h = blockIdx.y, bz = blockIdx.z;
    const int m0 = wid * 16;
    const unsigned FULL = 0xffffffffu;

    const float* Qg = g_q + ((size_t)(bz * HH + h) * SS + qt * 128) * HD;
    const float* Kg = g_k + ((size_t)(bz * HH + h) * SS) * HD;
    const float* Vg = g_v + ((size_t)(bz * HH + h) * SS) * HD;

    // Stage Q (128x64) via Ps, pre-scale by 1/sqrt(64), cvt tf32
    {
        const float4* Q4 = (const float4*)Qg;
#pragma unroll
        for (int j = 0; j < 8; j++) {
            int i = tid + j * 256;            // 2048 float4
            float4 f = Q4[i];
            float* d = Ps + (i >> 4) * TST + (i & 15) * 4;
            d[0] = __uint_as_float(f2tf(f.x * 0.125f));
            d[1] = __uint_as_float(f2tf(f.y * 0.125f));
            d[2] = __uint_as_float(f2tf(f.z * 0.125f));
            d[3] = __uint_as_float(f2tf(f.w * 0.125f));
        }
    }
    __syncthreads();

    // Q A-fragments: a0=(g,t) a1=(g+8,t) a2=(g,t+4) a3=(g+8,t+4)
    uint32_t qf[8][4];
#pragma unroll
    for (int ks = 0; ks < 8; ks++) {
        const float* qp = Ps + (m0 + g) * TST + ks * 8 + t;
        qf[ks][0] = __float_as_uint(qp[0]);
        qf[ks][1] = __float_as_uint(qp[8 * TST]);
        qf[ks][2] = __float_as_uint(qp[4]);
        qf[ks][3] = __float_as_uint(qp[8 * TST + 4]);
    }

    float of[8][4];
#pragma unroll
    for (int i = 0; i < 8; i++)
#pragma unroll
        for (int j = 0; j < 4; j++) of[i][j] = 0.0f;
    float mrow[2] = { -1e30f, -1e30f };
    float lrow[2] = { 0.0f, 0.0f };

    for (int ktile = 0; ktile < SS / 64; ktile++) {
        __syncthreads();                       // prev PV reads of Vs/Ps done
        const float4* K4 = (const float4*)(Kg + (size_t)ktile * 64 * HD);
        const float4* V4 = (const float4*)(Vg + (size_t)ktile * 64 * HD);
#pragma unroll
        for (int j = 0; j < 4; j++) {
            int i = tid + j * 256;             // 1024 float4 each
            float4 fk = K4[i], fv = V4[i];
            float* dk = Ks + (i >> 4) * TST + (i & 15) * 4;
            float* dv = Vs + (i >> 4) * TST + (i & 15) * 4;
            dk[0] = __uint_as_float(f2tf(fk.x));
            dk[1] = __uint_as_float(f2tf(fk.y));
            dk[2] = __uint_as_float(f2tf(fk.z));
            dk[3] = __uint_as_float(f2tf(fk.w));
            dv[0] = __uint_as_float(f2tf(fv.x));
            dv[1] = __uint_as_float(f2tf(fv.y));
            dv[2] = __uint_as_float(f2tf(fv.z));
            dv[3] = __uint_as_float(f2tf(fv.w));
        }
        __syncthreads();

        // Score GEMM: S[16q x 64kc] = Q . K^T  (m=q, n=kc, k=d)
        float sf[8][4];
#pragma unroll
        for (int i = 0; i < 8; i++)
#pragma unroll
            for (int j = 0; j < 4; j++) sf[i][j] = 0.0f;
#pragma unroll
        for (int d8 = 0; d8 < 8; d8++) {
#pragma unroll
            for (int n8 = 0; n8 < 8; n8++) {
                uint32_t bf[2];
                const float* bp = Ks + (n8 * 8 + g) * TST + d8 * 8 + t;
                bf[0] = __float_as_uint(bp[0]);
                bf[1] = __float_as_uint(bp[4]);     // k=t+4 -> d+4
                mma8(sf[n8], qf[d8], bf);
            }
        }

        // Online softmax on fragments; write P (tf32) to per-warp Ps rows
        float alpha[2];
#pragma unroll
        for (int ri = 0; ri < 2; ri++) {
            float mt_ = -1e30f;
#pragma unroll
            for (int j = 0; j < 8; j++)
                mt_ = fmaxf(mt_, fmaxf(sf[j][ri * 2], sf[j][ri * 2 + 1]));
            mt_ = fmaxf(mt_, __shfl_xor_sync(FULL, mt_, 1));
            mt_ = fmaxf(mt_, __shfl_xor_sync(FULL, mt_, 2));
            const float mn = fmaxf(mrow[ri], mt_);
            alpha[ri] = __expf(mrow[ri] - mn);
            float ls = 0.0f;
            const int r = m0 + g + ri * 8;
#pragma unroll
            for (int j = 0; j < 8; j++) {
                const float e0 = __expf(sf[j][ri * 2 + 0] - mn);
                const float e1 = __expf(sf[j][ri * 2 + 1] - mn);
                ls += e0 + e1;
                float* pp = Ps + r * TST + j * 8 + 2 * t;
                pp[0] = __uint_as_float(f2tf(e0));
                pp[1] = __uint_as_float(f2tf(e1));
            }
            ls += __shfl_xor_sync(FULL, ls, 1);
            ls += __shfl_xor_sync(FULL, ls, 2);
            lrow[ri] = lrow[ri] * alpha[ri] + ls;
            mrow[ri] = mn;
        }
#pragma unroll
        for (int n8 = 0; n8 < 8; n8++) {
            of[n8][0] *= alpha[0]; of[n8][1] *= alpha[0];
            of[n8][2] *= alpha[1]; of[n8][3] *= alpha[1];
        }
        __syncwarp();   // P region is warp-private; make STS visible to lanes

        // PV GEMM: O[16q x 64d] += P . V  (m=q, n=d, k=kc)
#pragma unroll
        for (int k8 = 0; k8 < 8; k8++) {
            uint32_t pf[4];
            const float* pp = Ps + (m0 + g) * TST + k8 * 8 + t;
            pf[0] = __float_as_uint(pp[0]);
            pf[1] = __float_as_uint(pp[8 * TST]);
            pf[2] = __float_as_uint(pp[4]);
            pf[3] = __float_as_uint(pp[8 * TST + 4]);
#pragma unroll
            for (int n8 = 0; n8 < 8; n8++) {
                uint32_t bf[2];
                const float* vp = Vs + (k8 * 8 + t) * TST + n8 * 8 + g;
                bf[0] = __float_as_uint(vp[0]);
                bf[1] = __float_as_uint(vp[4 * TST]);   // k=t+4 -> kc+4
                mma8(of[n8], pf, bf);
            }
        }
    }

    // Write O / l to g_attn [B*S, D]
    const float inv0 = 1.0f / lrow[0];
    const float inv1 = 1.0f / lrow[1];
    const int row0 = bz * SS + qt * 128 + m0 + g;
#pragma unroll
    for (int n8 = 0; n8 < 8; n8++) {
        const int col = h * 64 + n8 * 8 + 2 * t;
        float2 v0, v1;
        v0.x = of[n8][0] * inv0; v0.y = of[n8][1] * inv0;
        v1.x = of[n8][2] * inv1; v1.y = of[n8][3] * inv1;
        *(float2*)&g_attn[(size_t)row0 * DD + col] = v0;
        *(float2*)&g_attn[(size_t)(row0 + 8) * DD + col] = v1;
    }
}

// ---------------------------------------------------------------------------
extern "C" void kernel_launch(void* const* d_in, const int* in_sizes, int n_in,
                              void* d_out, int out_size)
{
    const float* x      = (const float*)d_in[0];
    const float* w_qkv  = (const float*)d_in[1];
    const float* b_qkv  = (const float*)d_in[2];
    const float* w_proj = (const float*)d_in[3];
    const float* b_proj = (const float*)d_in[4];
    float* out = (float*)d_out;

    cudaFuncSetAttribute(tc_gemm,
                         cudaFuncAttributeMaxDynamicSharedMemorySize, GEMM_SMEM);
    cudaFuncSetAttribute(attn_kernel,
                         cudaFuncAttributeMaxDynamicSharedMemorySize, ATT_SMEM);

    // GEMM1: [4096,1024] @ [1024,3072] -> scatter Q/K/V (tf32 mma.sync)
    {
        dim3 grid(QKV_N / 128, M_ROWS / 128);
        tc_gemm<<<grid, 256, GEMM_SMEM>>>(x, w_qkv, b_qkv, nullptr,
                                          M_ROWS, QKV_N, DD, 1);
    }
    // Attention: 16 q-tiles x 16 heads x 2 batches
    {
        dim3 grid(SS / 128, HH, BB);
        attn_kernel<<<grid, 256, ATT_SMEM>>>();
    }
    // GEMM2: [4096,1024] @ [1024,1024] + bias -> out (tf32 mma.sync)
    {
        dim3 grid(DD / 128, M_ROWS / 128);
        tc_gemm<<<grid, 256, GEMM_SMEM>>>(nullptr, w_proj, b_proj, out,
                                          M_ROWS, DD, DD, 0);
    }
}

// round 8
// speedup vs baseline: 6.2068x; 1.1817x over previous
#include <cuda_runtime.h>
#include <cuda_bf16.h>
#include <cstdint>

// Problem constants
#define BB 2
#define SS 2048
#define DD 1024
#define HH 16
#define HD 64
#define M_ROWS (BB*SS)          // 4096
#define QKV_N  (3*DD)           // 3072

// Scratch (allocation-free: __device__ globals)
__device__ float g_q[BB*HH*SS*HD];     // [B,H,S,HD]
__device__ float g_k[BB*HH*SS*HD];
__device__ float g_v[BB*HH*SS*HD];
__device__ float g_attn[M_ROWS*DD];    // [B*S, D]

// ---------------------------------------------------------------------------
// tf32 helpers (plain sm_80+ PTX -- no 'a'-suffix features)
// ---------------------------------------------------------------------------
__device__ __forceinline__ uint32_t f2tf(float f) {
    uint32_t u;
    asm("cvt.rna.tf32.f32 %0, %1;" : "=r"(u) : "f"(f));
    return u;
}
__device__ __forceinline__ float f2tff(float f) { return __uint_as_float(f2tf(f)); }

// D += A(16x8 tf32) * B(8x8 tf32), fp32 accum
__device__ __forceinline__ void mma8(float c[4], const uint32_t a[4],
                                     uint32_t b0, uint32_t b1) {
    asm volatile(
        "mma.sync.aligned.m16n8k8.row.col.f32.tf32.tf32.f32 "
        "{%0,%1,%2,%3}, {%4,%5,%6,%7}, {%8,%9}, {%0,%1,%2,%3};"
        : "+f"(c[0]), "+f"(c[1]), "+f"(c[2]), "+f"(c[3])
        : "r"(a[0]), "r"(a[1]), "r"(a[2]), "r"(a[3]), "r"(b0), "r"(b1));
}
// ldmatrix x4: four 8x8 b16 matrices == four 8x4 f32 quadrants
__device__ __forceinline__ void ldsm4(uint32_t r[4], uint32_t addr) {
    asm volatile("ldmatrix.sync.aligned.m8n8.x4.shared.b16 {%0,%1,%2,%3}, [%4];"
        : "=r"(r[0]), "=r"(r[1]), "=r"(r[2]), "=r"(r[3]) : "r"(addr));
}
__device__ __forceinline__ uint32_t smem_u32(const void* p) {
    uint32_t a;
    asm("{ .reg .u64 t; cvta.to.shared.u64 t, %1; cvt.u32.u64 %0, t; }"
        : "=r"(a) : "l"(p));
    return a;
}

// ---------------------------------------------------------------------------
// tf32 mma.sync GEMM: C[M,N] = A[M,K] @ B[K,N] + bias
// CTA 128x128, BK=32, double-buffered. A smem [m][k] 32-f rows, B smem
// n-major [n][k] 32-f rows; both XOR-swizzled (16B chunk ^ (row&7)).
// All fragments via ldmatrix.x4. 8 warps as 4(m) x 2(n), warp tile 32x64.
// qkv_mode=1: scatter into g_q/g_k/g_v. A==nullptr -> read g_attn.
// ---------------------------------------------------------------------------
#define GEMM_SMEM (4*128*32*4)   // 65536 B

__global__ __launch_bounds__(256, 2) void tc_gemm(
    const float* __restrict__ A, const float* __restrict__ B,
    const float* __restrict__ bias, float* __restrict__ C,
    int M, int N, int K, int qkv_mode)
{
    extern __shared__ float sh[];
    float* As[2] = { sh,        sh + 4096 };
    float* Bs[2] = { sh + 8192, sh + 12288 };

    const int tid = threadIdx.x;
    const int wid = tid >> 5, lane = tid & 31;
    const int g = lane >> 2, t = lane & 3;
    const int lane15 = lane & 15;
    const int khalf = lane >> 4;          // 0: k0-3 chunk, 1: k4-7 chunk
    const int s7 = lane15 & 7;            // swizzle XOR for all frag rows
    const int bm = blockIdx.y, bn = blockIdx.x;
    const int wm = wid & 3, wn = wid >> 2;

    if (A == nullptr) A = g_attn;
    const float* Ablk = A + (size_t)bm * 128 * K;
    const float* Bblk = B + (size_t)bn * 128;

    const uint32_t asu[2] = { smem_u32(As[0]), smem_u32(As[1]) };
    const uint32_t bsu[2] = { smem_u32(Bs[0]), smem_u32(Bs[1]) };
    // lane base addresses (bytes): rows are 128B
    const uint32_t aofs0 = (uint32_t)(wm * 32 + lane15) * 128;
    const uint32_t aofs1 = aofs0 + 16 * 128;
    uint32_t bofs[4];
#pragma unroll
    for (int nb = 0; nb < 4; nb++)
        bofs[nb] = (uint32_t)(wn * 64 + nb * 16 + lane15) * 128;

    float acc[2][8][4];
#pragma unroll
    for (int i = 0; i < 2; i++)
#pragma unroll
        for (int j = 0; j < 8; j++)
#pragma unroll
            for (int k = 0; k < 4; k++) acc[i][j][k] = 0.0f;

    float4 ar[4];        // A prefetch
    float  br[16];       // B prefetch (4 n-points x 4 k)
    auto LDG = [&](int kt) {
#pragma unroll
        for (int i = 0; i < 4; i++) {       // A 128x32: thread -> (m, chunk)
            int idx = tid + i * 256;
            ar[i] = *(const float4*)(Ablk + (size_t)(idx >> 3) * K + kt * 32 + (idx & 7) * 4);
        }
#pragma unroll
        for (int i = 0; i < 4; i++) {       // B: thread -> (n, kgroup), 4 scalars along k
            int idx = tid + i * 256;
            const float* bp = Bblk + (size_t)(kt * 32 + (idx >> 7) * 4) * N + (idx & 127);
#pragma unroll
            for (int j = 0; j < 4; j++) br[i * 4 + j] = bp[(size_t)j * N];
        }
    };
    auto STS = [&](int p) {
#pragma unroll
        for (int i = 0; i < 4; i++) {
            int idx = tid + i * 256;
            int m = idx >> 3, ch = idx & 7;
            float* d = As[p] + m * 32 + ((ch ^ (m & 7)) * 4);
            d[0] = f2tff(ar[i].x); d[1] = f2tff(ar[i].y);
            d[2] = f2tff(ar[i].z); d[3] = f2tff(ar[i].w);
        }
#pragma unroll
        for (int i = 0; i < 4; i++) {
            int idx = tid + i * 256;
            int n = idx & 127, kg = idx >> 7;    // kg 0..7 (k chunk)
            float* d = Bs[p] + n * 32 + ((kg ^ (n & 7)) * 4);
            d[0] = f2tff(br[i * 4 + 0]); d[1] = f2tff(br[i * 4 + 1]);
            d[2] = f2tff(br[i * 4 + 2]); d[3] = f2tff(br[i * 4 + 3]);
        }
    };

    const int NT = K >> 5;
    LDG(0); STS(0);
    if (NT > 1) LDG(1);
    __syncthreads();

    for (int kt = 0; kt < NT; kt++) {
        const int p = kt & 1;
#pragma unroll
        for (int ks = 0; ks < 4; ks++) {
            const uint32_t chsw = (uint32_t)((ks * 2 + khalf) ^ s7) << 4;
            uint32_t af0[4], af1[4];
            ldsm4(af0, asu[p] + aofs0 + chsw);
            ldsm4(af1, asu[p] + aofs1 + chsw);
#pragma unroll
            for (int nb = 0; nb < 4; nb++) {
                uint32_t q[4];
                ldsm4(q, bsu[p] + bofs[nb] + chsw);
                mma8(acc[0][2*nb],   af0, q[0], q[2]);
                mma8(acc[1][2*nb],   af1, q[0], q[2]);
                mma8(acc[0][2*nb+1], af0, q[1], q[3]);
                mma8(acc[1][2*nb+1], af1, q[1], q[3]);
            }
        }
        if (kt + 1 < NT) {
            __syncthreads();
            STS((kt + 1) & 1);
            if (kt + 2 < NT) LDG(kt + 2);
            __syncthreads();
        }
    }

    // Epilogue: c0=(g,2t) c1=(g,2t+1) c2=(g+8,2t) c3=(g+8,2t+1)
#pragma unroll
    for (int mt = 0; mt < 2; mt++) {
#pragma unroll
        for (int half = 0; half < 2; half++) {
            const int row = bm * 128 + wm * 32 + mt * 16 + g + half * 8;
#pragma unroll
            for (int nt = 0; nt < 8; nt++) {
                const int col = bn * 128 + wn * 64 + nt * 8 + 2 * t;
                float2 v;
                v.x = acc[mt][nt][half * 2 + 0] + bias[col];
                v.y = acc[mt][nt][half * 2 + 1] + bias[col + 1];
                if (qkv_mode) {
                    const int b_ = row >> 11, s_ = row & 2047;
                    const int which = col >> 10;
                    const int h  = (col >> 6) & 15;
                    const int hd = col & 63;
                    float* dst = (which == 0) ? g_q : (which == 1) ? g_k : g_v;
                    *(float2*)&dst[(((size_t)(b_ * HH + h) * SS) + s_) * HD + hd] = v;
                } else {
                    *(float2*)&C[(size_t)row * N + col] = v;
                }
            }
        }
    }
}

// ---------------------------------------------------------------------------
// Flash attention, tf32 mma.sync + ldmatrix. CTA = (b,h,128 q); 8 warps x
// 16 q-rows. Smem (swizzled 64-f rows): Ks[kc][d] 16KB, Vsn[d][kc] 16KB
// (transposed at staging), Ps[q][*] 32KB (Q at init, then P per tile).
// ---------------------------------------------------------------------------
#define ATT_SMEM ((64*64 + 64*64 + 128*64)*4)   // 65536 B

__global__ __launch_bounds__(256, 2) void attn_kernel()
{
    extern __shared__ float sh[];
    float* Ks  = sh;                 // 4096 f
    float* Vsn = sh + 4096;          // 4096 f
    float* Ps  = sh + 8192;          // 8192 f
    const uint32_t ks_u = smem_u32(Ks);
    const uint32_t vs_u = smem_u32(Vsn);
    const uint32_t ps_u = smem_u32(Ps);

    const int tid = threadIdx.x;
    const int wid = tid >> 5, lane = tid & 31;
    const int g = lane >> 2, t = lane & 3;
    const int lane15 = lane & 15;
    const int khalf = lane >> 4;
    const int s7 = lane15 & 7;
    const int qt = blockIdx.x, h = blockIdx.y, bz = blockIdx.z;
    const int m0 = wid * 16;
    const unsigned FULL = 0xffffffffu;

    const float* Qg = g_q + ((size_t)(bz * HH + h) * SS + qt * 128) * HD;
    const float* Kg = g_k + ((size_t)(bz * HH + h) * SS) * HD;
    const float* Vg = g_v + ((size_t)(bz * HH + h) * SS) * HD;

    // Stage Q (128x64) into Ps, scale 1/8, tf32, swizzled
    {
        const float4* Q4 = (const float4*)Qg;
#pragma unroll
        for (int i = 0; i < 8; i++) {
            int idx = tid + i * 256;               // 2048 float4
            int row = idx >> 4, ch = idx & 15;
            float4 f = Q4[idx];
            float* d = Ps + row * 64 + ((ch ^ (row & 7)) * 4);
            d[0] = f2tff(f.x * 0.125f); d[1] = f2tff(f.y * 0.125f);
            d[2] = f2tff(f.z * 0.125f); d[3] = f2tff(f.w * 0.125f);
        }
    }
    __syncthreads();

    // Q A-fragments (persist in regs): rows m0..m0+15, 256B rows
    const uint32_t pofs = ps_u + (uint32_t)(m0 + lane15) * 256;
    uint32_t qf[8][4];
#pragma unroll
    for (int ks = 0; ks < 8; ks++)
        ldsm4(qf[ks], pofs + (((uint32_t)(ks * 2 + khalf) ^ s7) << 4));

    float of[8][4];
#pragma unroll
    for (int i = 0; i < 8; i++)
#pragma unroll
        for (int j = 0; j < 4; j++) of[i][j] = 0.0f;
    float mrow[2] = { -1e30f, -1e30f };
    float lrow[2] = { 0.0f, 0.0f };

    // lane frag base addrs for K / V (per nb); rows 256B
    uint32_t kofs[4], vofs[4];
#pragma unroll
    for (int nb = 0; nb < 4; nb++) {
        kofs[nb] = ks_u + (uint32_t)(nb * 16 + lane15) * 256;
        vofs[nb] = vs_u + (uint32_t)(nb * 16 + lane15) * 256;
    }

    for (int ktile = 0; ktile < SS / 64; ktile++) {
        __syncthreads();                       // prev tile reads done
        // Stage K natural [kc][d]
        {
            const float4* K4 = (const float4*)(Kg + (size_t)ktile * 64 * HD);
#pragma unroll
            for (int i = 0; i < 4; i++) {
                int idx = tid + i * 256;       // 1024 float4
                int row = idx >> 4, ch = idx & 15;
                float4 f = K4[idx];
                float* d = Ks + row * 64 + ((ch ^ (row & 7)) * 4);
                d[0] = f2tff(f.x); d[1] = f2tff(f.y);
                d[2] = f2tff(f.z); d[3] = f2tff(f.w);
            }
        }
        // Stage V transposed -> Vsn[d][kc]
        {
            const float* Vt = Vg + (size_t)ktile * 64 * HD;
#pragma unroll
            for (int i = 0; i < 4; i++) {
                int idx = tid + i * 256;
                int dcol = idx & 63, kg = idx >> 6;     // kg 0..15 (kc chunk)
                const float* vp = Vt + (size_t)(kg * 4) * HD + dcol;
                float* d = Vsn + dcol * 64 + ((kg ^ (dcol & 7)) * 4);
                d[0] = f2tff(vp[0]);
                d[1] = f2tff(vp[HD]);
                d[2] = f2tff(vp[2 * HD]);
                d[3] = f2tff(vp[3 * HD]);
            }
        }
        __syncthreads();

        // Score GEMM: S[16q x 64kc] = Q . K^T
        float sf[8][4];
#pragma unroll
        for (int i = 0; i < 8; i++)
#pragma unroll
            for (int j = 0; j < 4; j++) sf[i][j] = 0.0f;
#pragma unroll
        for (int d8 = 0; d8 < 8; d8++) {
            const uint32_t chsw = ((uint32_t)(d8 * 2 + khalf) ^ s7) << 4;
#pragma unroll
            for (int nb = 0; nb < 4; nb++) {
                uint32_t q[4];
                ldsm4(q, kofs[nb] + chsw);
                mma8(sf[2*nb],   qf[d8], q[0], q[2]);
                mma8(sf[2*nb+1], qf[d8], q[1], q[3]);
            }
        }

        // Online softmax; write P (tf32) to warp-private Ps rows (swizzled)
        float alpha[2];
#pragma unroll
        for (int ri = 0; ri < 2; ri++) {
            float mt_ = -1e30f;
#pragma unroll
            for (int j = 0; j < 8; j++)
                mt_ = fmaxf(mt_, fmaxf(sf[j][ri * 2], sf[j][ri * 2 + 1]));
            mt_ = fmaxf(mt_, __shfl_xor_sync(FULL, mt_, 1));
            mt_ = fmaxf(mt_, __shfl_xor_sync(FULL, mt_, 2));
            const float mn = fmaxf(mrow[ri], mt_);
            alpha[ri] = __expf(mrow[ri] - mn);
            float ls = 0.0f;
            const int r = m0 + g + ri * 8;
            float* prow = Ps + r * 64 + (t & 1) * 2;
#pragma unroll
            for (int j = 0; j < 8; j++) {
                const float e0 = __expf(sf[j][ri * 2 + 0] - mn);
                const float e1 = __expf(sf[j][ri * 2 + 1] - mn);
                ls += e0 + e1;
                // element (r, k=j*8+2t): chunk=j*2+(t>>1), pos=(2t)&3
                float2* pp = (float2*)(prow + (((j * 2 + (t >> 1)) ^ g) * 4));
                *pp = make_float2(f2tff(e0), f2tff(e1));
            }
            ls += __shfl_xor_sync(FULL, ls, 1);
            ls += __shfl_xor_sync(FULL, ls, 2);
            lrow[ri] = lrow[ri] * alpha[ri] + ls;
            mrow[ri] = mn;
        }
#pragma unroll
        for (int n8 = 0; n8 < 8; n8++) {
            of[n8][0] *= alpha[0]; of[n8][1] *= alpha[0];
            of[n8][2] *= alpha[1]; of[n8][3] *= alpha[1];
        }
        __syncwarp();   // P is warp-private; make STS visible to lanes

        // PV GEMM: O[16q x 64d] += P . V
#pragma unroll
        for (int k8 = 0; k8 < 8; k8++) {
            const uint32_t chsw = ((uint32_t)(k8 * 2 + khalf) ^ s7) << 4;
            uint32_t pf[4];
            ldsm4(pf, pofs + chsw);
#pragma unroll
            for (int nb = 0; nb < 4; nb++) {
                uint32_t q[4];
                ldsm4(q, vofs[nb] + chsw);
                mma8(of[2*nb],   pf, q[0], q[2]);
                mma8(of[2*nb+1], pf, q[1], q[3]);
            }
        }
    }

    // Write O to g_attn [B*S, D]
    const float inv0 = 1.0f / lrow[0];
    const float inv1 = 1.0f / lrow[1];
    const int row0 = bz * SS + qt * 128 + m0 + g;
#pragma unroll
    for (int n8 = 0; n8 < 8; n8++) {
        const int col = h * 64 + n8 * 8 + 2 * t;
        float2 v0, v1;
        v0.x = of[n8][0] * inv0; v0.y = of[n8][1] * inv0;
        v1.x = of[n8][2] * inv1; v1.y = of[n8][3] * inv1;
        *(float2*)&g_attn[(size_t)row0 * DD + col] = v0;
        *(float2*)&g_attn[(size_t)(row0 + 8) * DD + col] = v1;
    }
}

// ---------------------------------------------------------------------------
extern "C" void kernel_launch(void* const* d_in, const int* in_sizes, int n_in,
                              void* d_out, int out_size)
{
    const float* x      = (const float*)d_in[0];
    const float* w_qkv  = (const float*)d_in[1];
    const float* b_qkv  = (const float*)d_in[2];
    const float* w_proj = (const float*)d_in[3];
    const float* b_proj = (const float*)d_in[4];
    float* out = (float*)d_out;

    cudaFuncSetAttribute(tc_gemm,
                         cudaFuncAttributeMaxDynamicSharedMemorySize, GEMM_SMEM);
    cudaFuncSetAttribute(attn_kernel,
                         cudaFuncAttributeMaxDynamicSharedMemorySize, ATT_SMEM);

    // GEMM1: [4096,1024] @ [1024,3072] -> scatter Q/K/V
    {
        dim3 grid(QKV_N / 128, M_ROWS / 128);
        tc_gemm<<<grid, 256, GEMM_SMEM>>>(x, w_qkv, b_qkv, nullptr,
                                          M_ROWS, QKV_N, DD, 1);
    }
    // Attention: 16 q-tiles x 16 heads x 2 batches
    {
        dim3 grid(SS / 128, HH, BB);
        attn_kernel<<<grid, 256, ATT_SMEM>>>();
    }
    // GEMM2: [4096,1024] @ [1024,1024] + bias -> out
    {
        dim3 grid(DD / 128, M_ROWS / 128);
        tc_gemm<<<grid, 256, GEMM_SMEM>>>(nullptr, w_proj, b_proj, out,
                                          M_ROWS, DD, DD, 0);
    }
}

// round 9
// speedup vs baseline: 7.3782x; 1.1887x over previous
#include <cuda_runtime.h>
#include <cuda_bf16.h>
#include <cstdint>

// Problem constants
#define BB 2
#define SS 2048
#define DD 1024
#define HH 16
#define HD 64
#define M_ROWS (BB*SS)          // 4096
#define QKV_N  (3*DD)           // 3072

// Scratch (allocation-free: __device__ globals)
__device__ float g_q[BB*HH*SS*HD];     // [B,H,S,HD]  (pre-scaled by 1/8)
__device__ float g_k[BB*HH*SS*HD];     // [B,H,S,HD]
__device__ float g_v[BB*HH*SS*HD];     // [B,H,HD,S]  (d-major!)
__device__ float g_attn[M_ROWS*DD];    // [B*S, D]
__device__ float g_wqkvT[QKV_N*DD];    // [n][k], tf32-rounded
__device__ float g_wprojT[DD*DD];      // [n][k], tf32-rounded

// ---------------------------------------------------------------------------
// helpers (plain sm_80+ PTX -- no 'a'-suffix features)
// ---------------------------------------------------------------------------
__device__ __forceinline__ uint32_t f2tf(float f) {
    uint32_t u;
    asm("cvt.rna.tf32.f32 %0, %1;" : "=r"(u) : "f"(f));
    return u;
}
__device__ __forceinline__ float f2tff(float f) { return __uint_as_float(f2tf(f)); }
__device__ __forceinline__ void cvt4(uint32_t r[4]) {
#pragma unroll
    for (int i = 0; i < 4; i++) r[i] = f2tf(__uint_as_float(r[i]));
}
__device__ __forceinline__ void mma8(float c[4], const uint32_t a[4],
                                     uint32_t b0, uint32_t b1) {
    asm volatile(
        "mma.sync.aligned.m16n8k8.row.col.f32.tf32.tf32.f32 "
        "{%0,%1,%2,%3}, {%4,%5,%6,%7}, {%8,%9}, {%0,%1,%2,%3};"
        : "+f"(c[0]), "+f"(c[1]), "+f"(c[2]), "+f"(c[3])
        : "r"(a[0]), "r"(a[1]), "r"(a[2]), "r"(a[3]), "r"(b0), "r"(b1));
}
__device__ __forceinline__ void ldsm4(uint32_t r[4], uint32_t addr) {
    asm volatile("ldmatrix.sync.aligned.m8n8.x4.shared.b16 {%0,%1,%2,%3}, [%4];"
        : "=r"(r[0]), "=r"(r[1]), "=r"(r[2]), "=r"(r[3]) : "r"(addr));
}
__device__ __forceinline__ uint32_t smem_u32(const void* p) {
    uint32_t a;
    asm("{ .reg .u64 t; cvta.to.shared.u64 t, %1; cvt.u32.u64 %0, t; }"
        : "=r"(a) : "l"(p));
    return a;
}
__device__ __forceinline__ void cpa16(uint32_t dst, const void* src) {
    asm volatile("cp.async.cg.shared.global [%0], [%1], 16;"
                 :: "r"(dst), "l"(src) : "memory");
}
__device__ __forceinline__ void cpa_commit() {
    asm volatile("cp.async.commit_group;" ::: "memory");
}
template<int N> __device__ __forceinline__ void cpa_wait() {
    asm volatile("cp.async.wait_group %0;" :: "n"(N) : "memory");
}

// ---------------------------------------------------------------------------
// Transpose + tf32-round: out[n*K + k] = tf32(in[k*N + n])
// ---------------------------------------------------------------------------
__global__ __launch_bounds__(256) void transpose_cvt(
    const float* __restrict__ in, float* __restrict__ out, int K, int N)
{
    __shared__ float tile[32][33];
    const int tx = threadIdx.x & 31, ty = threadIdx.x >> 5;   // 32 x 8
    const int k0 = blockIdx.y * 32, n0 = blockIdx.x * 32;
#pragma unroll
    for (int r = 0; r < 4; r++)
        tile[ty + r * 8][tx] = in[(size_t)(k0 + ty + r * 8) * N + n0 + tx];
    __syncthreads();
#pragma unroll
    for (int r = 0; r < 4; r++)
        out[(size_t)(n0 + ty + r * 8) * K + k0 + tx] = f2tff(tile[tx][ty + r * 8]);
}

// ---------------------------------------------------------------------------
// tf32 mma.sync GEMM: C[M,N] = A[M,K] @ Bt^T + bias   (Bt is [n][k] tf32)
// CTA 128x128, BK=32, 3-stage cp.async pipeline. A [m][k], B [n][k] smem,
// 128B rows, XOR swizzle (16B chunk ^ row&7). A cvt'd at fragment level.
// qkv_mode=1: B=g_wqkvT, scatter q(scaled)/k/v(d-major). 0: B=g_wprojT.
// ---------------------------------------------------------------------------
#define STAGES 3
#define GEMM_SMEM (STAGES * 32768)     // 96 KB

__global__ __launch_bounds__(256, 2) void tc_gemm(
    const float* __restrict__ A,
    const float* __restrict__ bias, float* __restrict__ C,
    int M, int N, int K, int qkv_mode)
{
    extern __shared__ float sh[];
    const uint32_t shu = smem_u32(sh);

    const int tid = threadIdx.x;
    const int wid = tid >> 5, lane = tid & 31;
    const int g = lane >> 2, t = lane & 3;
    const int lane15 = lane & 15;
    const int khalf = lane >> 4;
    const int s7 = lane15 & 7;
    const int bm = blockIdx.y, bn = blockIdx.x;
    const int wm = wid & 3, wn = wid >> 2;

    if (A == nullptr) A = g_attn;
    const float* Bt = qkv_mode ? g_wqkvT : g_wprojT;
    const float* Ablk = A + (size_t)bm * 128 * K;
    const float* Bblk = Bt + (size_t)bn * 128 * K;

    const uint32_t aofs0 = (uint32_t)(wm * 32 + lane15) * 128;
    const uint32_t aofs1 = aofs0 + 2048;
    uint32_t bofs[4];
#pragma unroll
    for (int nb = 0; nb < 4; nb++)
        bofs[nb] = 16384u + (uint32_t)(wn * 64 + nb * 16 + lane15) * 128;

    float acc[2][8][4];
#pragma unroll
    for (int i = 0; i < 2; i++)
#pragma unroll
        for (int j = 0; j < 8; j++)
#pragma unroll
            for (int k = 0; k < 4; k++) acc[i][j][k] = 0.0f;

    auto COPY = [&](int kt, int s) {
        const uint32_t ab = shu + (uint32_t)s * 32768u;
        const uint32_t bb = ab + 16384u;
#pragma unroll
        for (int i = 0; i < 4; i++) {
            int idx = tid + i * 256;
            int m = idx >> 3, ch = idx & 7;
            cpa16(ab + (uint32_t)m * 128u + (uint32_t)((ch ^ (m & 7)) << 4),
                  Ablk + (size_t)m * K + kt * 32 + ch * 4);
        }
#pragma unroll
        for (int i = 0; i < 4; i++) {
            int idx = tid + i * 256;
            int n = idx >> 3, ch = idx & 7;
            cpa16(bb + (uint32_t)n * 128u + (uint32_t)((ch ^ (n & 7)) << 4),
                  Bblk + (size_t)n * K + kt * 32 + ch * 4);
        }
    };

    const int NT = K >> 5;           // 32
    COPY(0, 0); cpa_commit();
    COPY(1, 1); cpa_commit();
    COPY(2, 2); cpa_commit();

    for (int kt = 0; kt < NT; kt++) {
        cpa_wait<2>();               // tiles <= kt complete
        __syncthreads();
        const uint32_t sb = shu + (uint32_t)(kt % STAGES) * 32768u;
#pragma unroll
        for (int ks = 0; ks < 4; ks++) {
            const uint32_t chsw = (uint32_t)((ks * 2 + khalf) ^ s7) << 4;
            uint32_t af0[4], af1[4];
            ldsm4(af0, sb + aofs0 + chsw);
            ldsm4(af1, sb + aofs1 + chsw);
            cvt4(af0); cvt4(af1);
#pragma unroll
            for (int nb = 0; nb < 4; nb++) {
                uint32_t q[4];
                ldsm4(q, sb + bofs[nb] + chsw);
                mma8(acc[0][2*nb],   af0, q[0], q[2]);
                mma8(acc[1][2*nb],   af1, q[0], q[2]);
                mma8(acc[0][2*nb+1], af0, q[1], q[3]);
                mma8(acc[1][2*nb+1], af1, q[1], q[3]);
            }
        }
        __syncthreads();             // stage kt%3 free for reuse
        if (kt + STAGES < NT) COPY(kt + STAGES, kt % STAGES);
        cpa_commit();                // always commit (empty groups ok)
    }

    // Epilogue: c0=(g,2t) c1=(g,2t+1) c2=(g+8,2t) c3=(g+8,2t+1)
#pragma unroll
    for (int mt = 0; mt < 2; mt++) {
#pragma unroll
        for (int half = 0; half < 2; half++) {
            const int row = bm * 128 + wm * 32 + mt * 16 + g + half * 8;
#pragma unroll
            for (int nt = 0; nt < 8; nt++) {
                const int col = bn * 128 + wn * 64 + nt * 8 + 2 * t;
                float2 v;
                v.x = acc[mt][nt][half * 2 + 0] + bias[col];
                v.y = acc[mt][nt][half * 2 + 1] + bias[col + 1];
                if (qkv_mode) {
                    const int b_ = row >> 11, s_ = row & 2047;
                    const int which = col >> 10;
                    const int h  = (col >> 6) & 15;
                    const int hd = col & 63;
                    if (which == 0) {          // Q: fold 1/sqrt(64)
                        v.x *= 0.125f; v.y *= 0.125f;
                        *(float2*)&g_q[(((size_t)(b_ * HH + h) * SS) + s_) * HD + hd] = v;
                    } else if (which == 1) {   // K
                        *(float2*)&g_k[(((size_t)(b_ * HH + h) * SS) + s_) * HD + hd] = v;
                    } else {                   // V: d-major [b,h,d,s]
                        float* dst = g_v + (((size_t)(b_ * HH + h) * HD) + hd) * SS + s_;
                        dst[0]  = v.x;
                        dst[SS] = v.y;
                    }
                } else {
                    *(float2*)&C[(size_t)row * N + col] = v;
                }
            }
        }
    }
}

// ---------------------------------------------------------------------------
// Flash attention, tf32 mma.sync + ldmatrix + cp.async double buffering.
// CTA = (b,h,128 q); 8 warps x 16 q-rows. Smem (bytes): Ks[2] @0/16384,
// Vs[2] @32768/49152, Ps @65536 (Q at init then per-warp P). Q pre-scaled
// by GEMM1; raw f32 staged, cvt at fragment level.
// ---------------------------------------------------------------------------
#define ATT_SMEM 98304

__global__ __launch_bounds__(256, 2) void attn_kernel()
{
    extern __shared__ float sh[];
    const uint32_t shu = smem_u32(sh);
    const uint32_t ps_u = shu + 65536u;
    float* Ps = sh + 16384;

    const int tid = threadIdx.x;
    const int wid = tid >> 5, lane = tid & 31;
    const int g = lane >> 2, t = lane & 3;
    const int lane15 = lane & 15;
    const int khalf = lane >> 4;
    const int s7 = lane15 & 7;
    const int qt = blockIdx.x, h = blockIdx.y, bz = blockIdx.z;
    const int m0 = wid * 16;
    const unsigned FULL = 0xffffffffu;

    const float* Qg = g_q + ((size_t)(bz * HH + h) * SS + qt * 128) * HD;
    const float* Kg = g_k + ((size_t)(bz * HH + h) * SS) * HD;
    const float* Vg = g_v + ((size_t)(bz * HH + h) * HD) * SS;   // [d][s]

    auto COPY_KV = [&](int kt, int s) {
        const uint32_t kb = shu + (uint32_t)s * 16384u;
        const uint32_t vb = shu + 32768u + (uint32_t)s * 16384u;
#pragma unroll
        for (int i = 0; i < 4; i++) {
            int idx = tid + i * 256;
            int row = idx >> 4, ch = idx & 15;
            cpa16(kb + (uint32_t)row * 256u + (uint32_t)((ch ^ (row & 7)) << 4),
                  Kg + (size_t)(kt * 64 + row) * HD + ch * 4);
        }
#pragma unroll
        for (int i = 0; i < 4; i++) {
            int idx = tid + i * 256;
            int d = idx >> 4, ch = idx & 15;
            cpa16(vb + (uint32_t)d * 256u + (uint32_t)((ch ^ (d & 7)) << 4),
                  Vg + (size_t)d * SS + kt * 64 + ch * 4);
        }
    };

    // Stage Q (raw, pre-scaled) into Ps
#pragma unroll
    for (int i = 0; i < 8; i++) {
        int idx = tid + i * 256;
        int row = idx >> 4, ch = idx & 15;
        cpa16(ps_u + (uint32_t)row * 256u + (uint32_t)((ch ^ (row & 7)) << 4),
              Qg + (size_t)row * HD + ch * 4);
    }
    cpa_commit();
    COPY_KV(0, 0); cpa_commit();
    cpa_wait<1>();                 // Q done (KV0 may pend)
    __syncthreads();

    // Q A-fragments (persist in regs), cvt once
    const uint32_t pofs = ps_u + (uint32_t)(m0 + lane15) * 256u;
    uint32_t qf[8][4];
#pragma unroll
    for (int ks = 0; ks < 8; ks++) {
        ldsm4(qf[ks], pofs + (((uint32_t)(ks * 2 + khalf) ^ s7) << 4));
        cvt4(qf[ks]);
    }

    float of[8][4];
#pragma unroll
    for (int i = 0; i < 8; i++)
#pragma unroll
        for (int j = 0; j < 4; j++) of[i][j] = 0.0f;
    float mrow[2] = { -1e30f, -1e30f };
    float lrow[2] = { 0.0f, 0.0f };

    uint32_t fofs[4];
#pragma unroll
    for (int nb = 0; nb < 4; nb++)
        fofs[nb] = (uint32_t)(nb * 16 + lane15) * 256u;

    for (int ktile = 0; ktile < SS / 64; ktile++) {
        __syncthreads();                       // slot (ktile+1)&1 free everywhere
        if (ktile + 1 < SS / 64) COPY_KV(ktile + 1, (ktile + 1) & 1);
        cpa_commit();
        cpa_wait<1>();                         // tile ktile complete
        __syncthreads();
        const uint32_t ksu = shu + (uint32_t)(ktile & 1) * 16384u;
        const uint32_t vsu = shu + 32768u + (uint32_t)(ktile & 1) * 16384u;

        // Score GEMM: S[16q x 64kc] = Q . K^T   (K frags cvt'd)
        float sf[8][4];
#pragma unroll
        for (int i = 0; i < 8; i++)
#pragma unroll
            for (int j = 0; j < 4; j++) sf[i][j] = 0.0f;
#pragma unroll
        for (int d8 = 0; d8 < 8; d8++) {
            const uint32_t chsw = ((uint32_t)(d8 * 2 + khalf) ^ s7) << 4;
#pragma unroll
            for (int nb = 0; nb < 4; nb++) {
                uint32_t q[4];
                ldsm4(q, ksu + fofs[nb] + chsw);
                cvt4(q);
                mma8(sf[2*nb],   qf[d8], q[0], q[2]);
                mma8(sf[2*nb+1], qf[d8], q[1], q[3]);
            }
        }

        // Online softmax; write P (tf32) to warp-private Ps rows (swizzled)
        float alpha[2];
#pragma unroll
        for (int ri = 0; ri < 2; ri++) {
            float mt_ = -1e30f;
#pragma unroll
            for (int j = 0; j < 8; j++)
                mt_ = fmaxf(mt_, fmaxf(sf[j][ri * 2], sf[j][ri * 2 + 1]));
            mt_ = fmaxf(mt_, __shfl_xor_sync(FULL, mt_, 1));
            mt_ = fmaxf(mt_, __shfl_xor_sync(FULL, mt_, 2));
            const float mn = fmaxf(mrow[ri], mt_);
            alpha[ri] = __expf(mrow[ri] - mn);
            float ls = 0.0f;
            const int r = m0 + g + ri * 8;
            float* prow = Ps + r * 64 + (t & 1) * 2;
#pragma unroll
            for (int j = 0; j < 8; j++) {
                const float e0 = __expf(sf[j][ri * 2 + 0] - mn);
                const float e1 = __expf(sf[j][ri * 2 + 1] - mn);
                ls += e0 + e1;
                float2* pp = (float2*)(prow + (((j * 2 + (t >> 1)) ^ g) * 4));
                *pp = make_float2(f2tff(e0), f2tff(e1));
            }
            ls += __shfl_xor_sync(FULL, ls, 1);
            ls += __shfl_xor_sync(FULL, ls, 2);
            lrow[ri] = lrow[ri] * alpha[ri] + ls;
            mrow[ri] = mn;
        }
#pragma unroll
        for (int n8 = 0; n8 < 8; n8++) {
            of[n8][0] *= alpha[0]; of[n8][1] *= alpha[0];
            of[n8][2] *= alpha[1]; of[n8][3] *= alpha[1];
        }
        __syncwarp();   // P is warp-private; make STS visible to lanes

        // PV GEMM: O[16q x 64d] += P . V   (V frags cvt'd)
#pragma unroll
        for (int k8 = 0; k8 < 8; k8++) {
            const uint32_t chsw = ((uint32_t)(k8 * 2 + khalf) ^ s7) << 4;
            uint32_t pf[4];
            ldsm4(pf, pofs + chsw);
#pragma unroll
            for (int nb = 0; nb < 4; nb++) {
                uint32_t q[4];
                ldsm4(q, vsu + fofs[nb] + chsw);
                cvt4(q);
                mma8(of[2*nb],   pf, q[0], q[2]);
                mma8(of[2*nb+1], pf, q[1], q[3]);
            }
        }
    }

    // Write O to g_attn [B*S, D]
    const float inv0 = 1.0f / lrow[0];
    const float inv1 = 1.0f / lrow[1];
    const int row0 = bz * SS + qt * 128 + m0 + g;
#pragma unroll
    for (int n8 = 0; n8 < 8; n8++) {
        const int col = h * 64 + n8 * 8 + 2 * t;
        float2 v0, v1;
        v0.x = of[n8][0] * inv0; v0.y = of[n8][1] * inv0;
        v1.x = of[n8][2] * inv1; v1.y = of[n8][3] * inv1;
        *(float2*)&g_attn[(size_t)row0 * DD + col] = v0;
        *(float2*)&g_attn[(size_t)(row0 + 8) * DD + col] = v1;
    }
}

// ---------------------------------------------------------------------------
extern "C" void kernel_launch(void* const* d_in, const int* in_sizes, int n_in,
                              void* d_out, int out_size)
{
    const float* x      = (const float*)d_in[0];
    const float* w_qkv  = (const float*)d_in[1];
    const float* b_qkv  = (const float*)d_in[2];
    const float* w_proj = (const float*)d_in[3];
    const float* b_proj = (const float*)d_in[4];
    float* out = (float*)d_out;

    cudaFuncSetAttribute(tc_gemm,
                         cudaFuncAttributeMaxDynamicSharedMemorySize, GEMM_SMEM);
    cudaFuncSetAttribute(attn_kernel,
                         cudaFuncAttributeMaxDynamicSharedMemorySize, ATT_SMEM);

    // Pre-transpose + tf32-round weights -> [n][k]
    {
        float* wt1; cudaGetSymbolAddress((void**)&wt1, g_wqkvT);
        float* wt2; cudaGetSymbolAddress((void**)&wt2, g_wprojT);
        dim3 t1(QKV_N / 32, DD / 32);
        transpose_cvt<<<t1, 256>>>(w_qkv, wt1, DD, QKV_N);
        dim3 t2(DD / 32, DD / 32);
        transpose_cvt<<<t2, 256>>>(w_proj, wt2, DD, DD);
    }
    // GEMM1: [4096,1024] @ [1024,3072] -> scatter Q(scaled)/K/V(d-major)
    {
        dim3 grid(QKV_N / 128, M_ROWS / 128);
        tc_gemm<<<grid, 256, GEMM_SMEM>>>(x, b_qkv, nullptr,
                                          M_ROWS, QKV_N, DD, 1);
    }
    // Attention: 16 q-tiles x 16 heads x 2 batches
    {
        dim3 grid(SS / 128, HH, BB);
        attn_kernel<<<grid, 256, ATT_SMEM>>>();
    }
    // GEMM2: [4096,1024] @ [1024,1024] + bias -> out
    {
        dim3 grid(DD / 128, M_ROWS / 128);
        tc_gemm<<<grid, 256, GEMM_SMEM>>>(nullptr, b_proj, out,
                                          M_ROWS, DD, DD, 0);
    }
}

// round 10
// speedup vs baseline: 8.4187x; 1.1410x over previous
#include <cuda_runtime.h>
#include <cuda_bf16.h>
#include <cstdint>

// Problem constants
#define BB 2
#define SS 2048
#define DD 1024
#define HH 16
#define HD 64
#define M_ROWS (BB*SS)          // 4096
#define QKV_N  (3*DD)           // 3072

// Scratch (allocation-free: __device__ globals). All tf32-rounded at write.
__device__ float g_q[BB*HH*SS*HD];     // [B,H,S,HD]  scaled by log2e/8, tf32
__device__ float g_k[BB*HH*SS*HD];     // [B,H,S,HD]  tf32
__device__ float g_v[BB*HH*SS*HD];     // [B,H,HD,S]  d-major, tf32
__device__ float g_attn[M_ROWS*DD];    // [B*S, D]    tf32
__device__ float g_xr[M_ROWS*DD];      // x, tf32
__device__ float g_wqkvT[QKV_N*DD];    // [n][k], tf32
__device__ float g_wprojT[DD*DD];      // [n][k], tf32

#define QSCALE 0.180336880523479f      // 0.125 * log2(e)

// ---------------------------------------------------------------------------
// helpers (plain sm_80+ PTX -- no 'a'-suffix features)
// ---------------------------------------------------------------------------
__device__ __forceinline__ uint32_t f2tf(float f) {
    uint32_t u;
    asm("cvt.rna.tf32.f32 %0, %1;" : "=r"(u) : "f"(f));
    return u;
}
__device__ __forceinline__ float f2tff(float f) { return __uint_as_float(f2tf(f)); }
__device__ __forceinline__ float ex2(float x) {
    float y;
    asm("ex2.approx.f32 %0, %1;" : "=f"(y) : "f"(x));
    return y;
}
__device__ __forceinline__ void mma8(float c[4], const uint32_t a[4],
                                     uint32_t b0, uint32_t b1) {
    asm volatile(
        "mma.sync.aligned.m16n8k8.row.col.f32.tf32.tf32.f32 "
        "{%0,%1,%2,%3}, {%4,%5,%6,%7}, {%8,%9}, {%0,%1,%2,%3};"
        : "+f"(c[0]), "+f"(c[1]), "+f"(c[2]), "+f"(c[3])
        : "r"(a[0]), "r"(a[1]), "r"(a[2]), "r"(a[3]), "r"(b0), "r"(b1));
}
__device__ __forceinline__ void ldsm4(uint32_t r[4], uint32_t addr) {
    asm volatile("ldmatrix.sync.aligned.m8n8.x4.shared.b16 {%0,%1,%2,%3}, [%4];"
        : "=r"(r[0]), "=r"(r[1]), "=r"(r[2]), "=r"(r[3]) : "r"(addr));
}
__device__ __forceinline__ uint32_t smem_u32(const void* p) {
    uint32_t a;
    asm("{ .reg .u64 t; cvta.to.shared.u64 t, %1; cvt.u32.u64 %0, t; }"
        : "=r"(a) : "l"(p));
    return a;
}
__device__ __forceinline__ void cpa16(uint32_t dst, const void* src) {
    asm volatile("cp.async.cg.shared.global [%0], [%1], 16;"
                 :: "r"(dst), "l"(src) : "memory");
}
__device__ __forceinline__ void cpa_commit() {
    asm volatile("cp.async.commit_group;" ::: "memory");
}
template<int N> __device__ __forceinline__ void cpa_wait() {
    asm volatile("cp.async.wait_group %0;" :: "n"(N) : "memory");
}

// ---------------------------------------------------------------------------
// Elementwise tf32-round: g_xr = rna(x)
// ---------------------------------------------------------------------------
__global__ __launch_bounds__(256) void round_x(const float* __restrict__ in)
{
    const int i = blockIdx.x * 256 + threadIdx.x;
    float4 f = ((const float4*)in)[i];
    f.x = f2tff(f.x); f.y = f2tff(f.y); f.z = f2tff(f.z); f.w = f2tff(f.w);
    ((float4*)g_xr)[i] = f;
}

// ---------------------------------------------------------------------------
// Transpose + tf32-round: out[n*K + k] = tf32(in[k*N + n])
// ---------------------------------------------------------------------------
__global__ __launch_bounds__(256) void transpose_cvt(
    const float* __restrict__ in, float* __restrict__ out, int K, int N)
{
    __shared__ float tile[32][33];
    const int tx = threadIdx.x & 31, ty = threadIdx.x >> 5;   // 32 x 8
    const int k0 = blockIdx.y * 32, n0 = blockIdx.x * 32;
#pragma unroll
    for (int r = 0; r < 4; r++)
        tile[ty + r * 8][tx] = in[(size_t)(k0 + ty + r * 8) * N + n0 + tx];
    __syncthreads();
#pragma unroll
    for (int r = 0; r < 4; r++)
        out[(size_t)(n0 + ty + r * 8) * K + k0 + tx] = f2tff(tile[tx][ty + r * 8]);
}

// ---------------------------------------------------------------------------
// tf32 mma.sync GEMM: C[M,N] = A[M,K] @ Bt^T + bias   (all inputs pre-tf32)
// CTA 128x128, BK=32, 3-stage cp.async pipeline, XOR-swizzled smem,
// ldmatrix fragments, ZERO in-loop cvts.
// qkv_mode=1: A=g_xr, B=g_wqkvT, scatter q(scaled,tf32)/k(tf32)/v(d-major,
// tf32). qkv_mode=0: A=g_attn, B=g_wprojT, C=out (full fp32).
// ---------------------------------------------------------------------------
#define STAGES 3
#define GEMM_SMEM (STAGES * 32768)     // 96 KB

__global__ __launch_bounds__(256, 2) void tc_gemm(
    const float* __restrict__ bias, float* __restrict__ C,
    int M, int N, int K, int qkv_mode)
{
    extern __shared__ float sh[];
    const uint32_t shu = smem_u32(sh);

    const int tid = threadIdx.x;
    const int wid = tid >> 5, lane = tid & 31;
    const int g = lane >> 2, t = lane & 3;
    const int lane15 = lane & 15;
    const int khalf = lane >> 4;
    const int s7 = lane15 & 7;
    const int bm = blockIdx.y, bn = blockIdx.x;
    const int wm = wid & 3, wn = wid >> 2;

    const float* A  = qkv_mode ? g_xr    : g_attn;
    const float* Bt = qkv_mode ? g_wqkvT : g_wprojT;
    const float* Ablk = A + (size_t)bm * 128 * K;
    const float* Bblk = Bt + (size_t)bn * 128 * K;

    const uint32_t aofs0 = (uint32_t)(wm * 32 + lane15) * 128;
    const uint32_t aofs1 = aofs0 + 2048;
    uint32_t bofs[4];
#pragma unroll
    for (int nb = 0; nb < 4; nb++)
        bofs[nb] = 16384u + (uint32_t)(wn * 64 + nb * 16 + lane15) * 128;

    float acc[2][8][4];
#pragma unroll
    for (int i = 0; i < 2; i++)
#pragma unroll
        for (int j = 0; j < 8; j++)
#pragma unroll
            for (int k = 0; k < 4; k++) acc[i][j][k] = 0.0f;

    auto COPY = [&](int kt, int s) {
        const uint32_t ab = shu + (uint32_t)s * 32768u;
        const uint32_t bb = ab + 16384u;
#pragma unroll
        for (int i = 0; i < 4; i++) {
            int idx = tid + i * 256;
            int m = idx >> 3, ch = idx & 7;
            cpa16(ab + (uint32_t)m * 128u + (uint32_t)((ch ^ (m & 7)) << 4),
                  Ablk + (size_t)m * K + kt * 32 + ch * 4);
        }
#pragma unroll
        for (int i = 0; i < 4; i++) {
            int idx = tid + i * 256;
            int n = idx >> 3, ch = idx & 7;
            cpa16(bb + (uint32_t)n * 128u + (uint32_t)((ch ^ (n & 7)) << 4),
                  Bblk + (size_t)n * K + kt * 32 + ch * 4);
        }
    };

    const int NT = K >> 5;           // 32
    COPY(0, 0); cpa_commit();
    COPY(1, 1); cpa_commit();
    COPY(2, 2); cpa_commit();

    for (int kt = 0; kt < NT; kt++) {
        cpa_wait<2>();
        __syncthreads();
        const uint32_t sb = shu + (uint32_t)(kt % STAGES) * 32768u;
#pragma unroll
        for (int ks = 0; ks < 4; ks++) {
            const uint32_t chsw = (uint32_t)((ks * 2 + khalf) ^ s7) << 4;
            uint32_t af0[4], af1[4];
            ldsm4(af0, sb + aofs0 + chsw);
            ldsm4(af1, sb + aofs1 + chsw);
#pragma unroll
            for (int nb = 0; nb < 4; nb++) {
                uint32_t q[4];
                ldsm4(q, sb + bofs[nb] + chsw);
                mma8(acc[0][2*nb],   af0, q[0], q[2]);
                mma8(acc[1][2*nb],   af1, q[0], q[2]);
                mma8(acc[0][2*nb+1], af0, q[1], q[3]);
                mma8(acc[1][2*nb+1], af1, q[1], q[3]);
            }
        }
        __syncthreads();
        if (kt + STAGES < NT) COPY(kt + STAGES, kt % STAGES);
        cpa_commit();
    }

    // Epilogue: c0=(g,2t) c1=(g,2t+1) c2=(g+8,2t) c3=(g+8,2t+1)
#pragma unroll
    for (int mt = 0; mt < 2; mt++) {
#pragma unroll
        for (int half = 0; half < 2; half++) {
            const int row = bm * 128 + wm * 32 + mt * 16 + g + half * 8;
#pragma unroll
            for (int nt = 0; nt < 8; nt++) {
                const int col = bn * 128 + wn * 64 + nt * 8 + 2 * t;
                float2 v;
                v.x = acc[mt][nt][half * 2 + 0] + bias[col];
                v.y = acc[mt][nt][half * 2 + 1] + bias[col + 1];
                if (qkv_mode) {
                    const int b_ = row >> 11, s_ = row & 2047;
                    const int which = col >> 10;
                    const int h  = (col >> 6) & 15;
                    const int hd = col & 63;
                    if (which == 0) {          // Q: fold log2e/8, round tf32
                        v.x = f2tff(v.x * QSCALE);
                        v.y = f2tff(v.y * QSCALE);
                        *(float2*)&g_q[(((size_t)(b_ * HH + h) * SS) + s_) * HD + hd] = v;
                    } else if (which == 1) {   // K: round tf32
                        v.x = f2tff(v.x); v.y = f2tff(v.y);
                        *(float2*)&g_k[(((size_t)(b_ * HH + h) * SS) + s_) * HD + hd] = v;
                    } else {                   // V: d-major, round tf32
                        float* dst = g_v + (((size_t)(b_ * HH + h) * HD) + hd) * SS + s_;
                        dst[0]  = f2tff(v.x);
                        dst[SS] = f2tff(v.y);
                    }
                } else {
                    *(float2*)&C[(size_t)row * N + col] = v;
                }
            }
        }
    }
}

// ---------------------------------------------------------------------------
// Flash attention, tf32 mma.sync + ldmatrix + cp.async double buffering.
// All streamed data (Q/K/V) pre-rounded to tf32 => no in-loop cvts.
// Softmax in log2 domain (Q pre-scaled by log2e/8, raw ex2.approx).
// Smem (bytes): Ks[2] @0/16384, Vs[2] @32768/49152, Ps @65536.
// ---------------------------------------------------------------------------
#define ATT_SMEM 98304

__global__ __launch_bounds__(256, 2) void attn_kernel()
{
    extern __shared__ float sh[];
    const uint32_t shu = smem_u32(sh);
    const uint32_t ps_u = shu + 65536u;
    float* Ps = sh + 16384;

    const int tid = threadIdx.x;
    const int wid = tid >> 5, lane = tid & 31;
    const int g = lane >> 2, t = lane & 3;
    const int lane15 = lane & 15;
    const int khalf = lane >> 4;
    const int s7 = lane15 & 7;
    const int qt = blockIdx.x, h = blockIdx.y, bz = blockIdx.z;
    const int m0 = wid * 16;
    const unsigned FULL = 0xffffffffu;

    const float* Qg = g_q + ((size_t)(bz * HH + h) * SS + qt * 128) * HD;
    const float* Kg = g_k + ((size_t)(bz * HH + h) * SS) * HD;
    const float* Vg = g_v + ((size_t)(bz * HH + h) * HD) * SS;   // [d][s]

    auto COPY_KV = [&](int kt, int s) {
        const uint32_t kb = shu + (uint32_t)s * 16384u;
        const uint32_t vb = shu + 32768u + (uint32_t)s * 16384u;
#pragma unroll
        for (int i = 0; i < 4; i++) {
            int idx = tid + i * 256;
            int row = idx >> 4, ch = idx & 15;
            cpa16(kb + (uint32_t)row * 256u + (uint32_t)((ch ^ (row & 7)) << 4),
                  Kg + (size_t)(kt * 64 + row) * HD + ch * 4);
        }
#pragma unroll
        for (int i = 0; i < 4; i++) {
            int idx = tid + i * 256;
            int d = idx >> 4, ch = idx & 15;
            cpa16(vb + (uint32_t)d * 256u + (uint32_t)((ch ^ (d & 7)) << 4),
                  Vg + (size_t)d * SS + kt * 64 + ch * 4);
        }
    };

    // Stage Q (pre-scaled, tf32) into Ps
#pragma unroll
    for (int i = 0; i < 8; i++) {
        int idx = tid + i * 256;
        int row = idx >> 4, ch = idx & 15;
        cpa16(ps_u + (uint32_t)row * 256u + (uint32_t)((ch ^ (row & 7)) << 4),
              Qg + (size_t)row * HD + ch * 4);
    }
    cpa_commit();
    COPY_KV(0, 0); cpa_commit();
    cpa_wait<1>();                 // Q done (KV0 may pend)
    __syncthreads();

    // Q A-fragments (persist in regs)
    const uint32_t pofs = ps_u + (uint32_t)(m0 + lane15) * 256u;
    uint32_t qf[8][4];
#pragma unroll
    for (int ks = 0; ks < 8; ks++)
        ldsm4(qf[ks], pofs + (((uint32_t)(ks * 2 + khalf) ^ s7) << 4));

    float of[8][4];
#pragma unroll
    for (int i = 0; i < 8; i++)
#pragma unroll
        for (int j = 0; j < 4; j++) of[i][j] = 0.0f;
    float mrow[2] = { -1e30f, -1e30f };
    float lrow[2] = { 0.0f, 0.0f };

    uint32_t fofs[4];
#pragma unroll
    for (int nb = 0; nb < 4; nb++)
        fofs[nb] = (uint32_t)(nb * 16 + lane15) * 256u;

    for (int ktile = 0; ktile < SS / 64; ktile++) {
        __syncthreads();
        if (ktile + 1 < SS / 64) COPY_KV(ktile + 1, (ktile + 1) & 1);
        cpa_commit();
        cpa_wait<1>();
        __syncthreads();
        const uint32_t ksu = shu + (uint32_t)(ktile & 1) * 16384u;
        const uint32_t vsu = shu + 32768u + (uint32_t)(ktile & 1) * 16384u;

        // Score GEMM: S[16q x 64kc] = Q . K^T  (log2 domain)
        float sf[8][4];
#pragma unroll
        for (int i = 0; i < 8; i++)
#pragma unroll
            for (int j = 0; j < 4; j++) sf[i][j] = 0.0f;
#pragma unroll
        for (int d8 = 0; d8 < 8; d8++) {
            const uint32_t chsw = ((uint32_t)(d8 * 2 + khalf) ^ s7) << 4;
#pragma unroll
            for (int nb = 0; nb < 4; nb++) {
                uint32_t q[4];
                ldsm4(q, ksu + fofs[nb] + chsw);
                mma8(sf[2*nb],   qf[d8], q[0], q[2]);
                mma8(sf[2*nb+1], qf[d8], q[1], q[3]);
            }
        }

        // Online softmax (base 2); write P (tf32) to warp-private Ps rows
        float alpha[2];
#pragma unroll
        for (int ri = 0; ri < 2; ri++) {
            float mt_ = -1e30f;
#pragma unroll
            for (int j = 0; j < 8; j++)
                mt_ = fmaxf(mt_, fmaxf(sf[j][ri * 2], sf[j][ri * 2 + 1]));
            mt_ = fmaxf(mt_, __shfl_xor_sync(FULL, mt_, 1));
            mt_ = fmaxf(mt_, __shfl_xor_sync(FULL, mt_, 2));
            const float mn = fmaxf(mrow[ri], mt_);
            alpha[ri] = ex2(mrow[ri] - mn);
            float ls = 0.0f;
            const int r = m0 + g + ri * 8;
            float* prow = Ps + r * 64 + (t & 1) * 2;
#pragma unroll
            for (int j = 0; j < 8; j++) {
                const float e0 = ex2(sf[j][ri * 2 + 0] - mn);
                const float e1 = ex2(sf[j][ri * 2 + 1] - mn);
                ls += e0 + e1;
                float2* pp = (float2*)(prow + (((j * 2 + (t >> 1)) ^ g) * 4));
                *pp = make_float2(f2tff(e0), f2tff(e1));
            }
            ls += __shfl_xor_sync(FULL, ls, 1);
            ls += __shfl_xor_sync(FULL, ls, 2);
            lrow[ri] = lrow[ri] * alpha[ri] + ls;
            mrow[ri] = mn;
        }
#pragma unroll
        for (int n8 = 0; n8 < 8; n8++) {
            of[n8][0] *= alpha[0]; of[n8][1] *= alpha[0];
            of[n8][2] *= alpha[1]; of[n8][3] *= alpha[1];
        }
        __syncwarp();   // P is warp-private; make STS visible to lanes

        // PV GEMM: O[16q x 64d] += P . V
#pragma unroll
        for (int k8 = 0; k8 < 8; k8++) {
            const uint32_t chsw = ((uint32_t)(k8 * 2 + khalf) ^ s7) << 4;
            uint32_t pf[4];
            ldsm4(pf, pofs + chsw);
#pragma unroll
            for (int nb = 0; nb < 4; nb++) {
                uint32_t q[4];
                ldsm4(q, vsu + fofs[nb] + chsw);
                mma8(of[2*nb],   pf, q[0], q[2]);
                mma8(of[2*nb+1], pf, q[1], q[3]);
            }
        }
    }

    // Write O to g_attn [B*S, D], tf32-rounded for GEMM2
    const float inv0 = 1.0f / lrow[0];
    const float inv1 = 1.0f / lrow[1];
    const int row0 = bz * SS + qt * 128 + m0 + g;
#pragma unroll
    for (int n8 = 0; n8 < 8; n8++) {
        const int col = h * 64 + n8 * 8 + 2 * t;
        float2 v0, v1;
        v0.x = f2tff(of[n8][0] * inv0); v0.y = f2tff(of[n8][1] * inv0);
        v1.x = f2tff(of[n8][2] * inv1); v1.y = f2tff(of[n8][3] * inv1);
        *(float2*)&g_attn[(size_t)row0 * DD + col] = v0;
        *(float2*)&g_attn[(size_t)(row0 + 8) * DD + col] = v1;
    }
}

// ---------------------------------------------------------------------------
extern "C" void kernel_launch(void* const* d_in, const int* in_sizes, int n_in,
                              void* d_out, int out_size)
{
    const float* x      = (const float*)d_in[0];
    const float* w_qkv  = (const float*)d_in[1];
    const float* b_qkv  = (const float*)d_in[2];
    const float* w_proj = (const float*)d_in[3];
    const float* b_proj = (const float*)d_in[4];
    float* out = (float*)d_out;

    cudaFuncSetAttribute(tc_gemm,
                         cudaFuncAttributeMaxDynamicSharedMemorySize, GEMM_SMEM);
    cudaFuncSetAttribute(attn_kernel,
                         cudaFuncAttributeMaxDynamicSharedMemorySize, ATT_SMEM);

    // Pre-round x; pre-transpose + round weights
    round_x<<<M_ROWS * DD / (256 * 4), 256>>>(x);
    {
        float* wt1; cudaGetSymbolAddress((void**)&wt1, g_wqkvT);
        float* wt2; cudaGetSymbolAddress((void**)&wt2, g_wprojT);
        dim3 t1(QKV_N / 32, DD / 32);
        transpose_cvt<<<t1, 256>>>(w_qkv, wt1, DD, QKV_N);
        dim3 t2(DD / 32, DD / 32);
        transpose_cvt<<<t2, 256>>>(w_proj, wt2, DD, DD);
    }
    // GEMM1: [4096,1024] @ [1024,3072] -> scatter Q(scaled)/K/V(d-major)
    {
        dim3 grid(QKV_N / 128, M_ROWS / 128);
        tc_gemm<<<grid, 256, GEMM_SMEM>>>(b_qkv, nullptr, M_ROWS, QKV_N, DD, 1);
    }
    // Attention: 16 q-tiles x 16 heads x 2 batches
    {
        dim3 grid(SS / 128, HH, BB);
        attn_kernel<<<grid, 256, ATT_SMEM>>>();
    }
    // GEMM2: [4096,1024] @ [1024,1024] + bias -> out
    {
        dim3 grid(DD / 128, M_ROWS / 128);
        tc_gemm<<<grid, 256, GEMM_SMEM>>>(b_proj, out, M_ROWS, DD, DD, 0);
    }
}